// round 15
// baseline (speedup 1.0000x reference)
#include <cuda_runtime.h>
#include <cuda_fp16.h>
#include <cstdint>

// Shapes fixed by dataset: B=64, E=16, D=64, Q_DIM=64 -> K=128.
#define B_DIM    64
#define K_DIM    128
#define NTILE    32
#define THREADS  128
#define HIST_CAP 262144
#define PITCH    136           // halves per row (272B): ldsm conflict-free
#define ABUF     17408         // Ah+Al per buffer
#define AL_DELTA 8704
#define NB_OFF   (16 * PITCH * 2)

// SMEM layout (bytes)
#define OFF_XH   0             // 64 x 136 halves = 17408
#define OFF_XL   17408
#define OFF_A    34816         // [Ah0,Al0][Ah1,Al1] = 2 x 17408
#define OFF_COLS 69632         // 2 x 32 ints
#define SMEM_TOTAL 70144

__device__ __half g_Xh[B_DIM * K_DIM];
__device__ __half g_Xl[B_DIM * K_DIM];
__device__ float  g_hist[HIST_CAP];
__device__ unsigned g_arr[2], g_dep[2];   // grid barrier state (self-resetting)

// ---------------------------------------------------------------------------
__device__ __forceinline__ uint32_t smem_u32(const void* p) {
    uint32_t a;
    asm("{ .reg .u64 t; cvta.to.shared.u64 t, %1; cvt.u32.u64 %0, t; }"
        : "=r"(a) : "l"(p));
    return a;
}

__device__ __forceinline__ uint32_t packh(float lo, float hi) {
    uint32_t r;
    asm("cvt.rn.f16x2.f32 %0, %1, %2;" : "=r"(r) : "f"(hi), "f"(lo));
    return r;
}

__device__ __forceinline__ void mma16816(float* d, const uint32_t* a,
                                         uint32_t b0, uint32_t b1) {
    asm volatile(
        "mma.sync.aligned.m16n8k16.row.col.f32.f16.f16.f32 "
        "{%0,%1,%2,%3}, {%4,%5,%6,%7}, {%8,%9}, {%0,%1,%2,%3};"
        : "+f"(d[0]), "+f"(d[1]), "+f"(d[2]), "+f"(d[3])
        : "r"(a[0]), "r"(a[1]), "r"(a[2]), "r"(a[3]), "r"(b0), "r"(b1));
}

__device__ __forceinline__ void ldsm4(uint32_t* r, uint32_t addr) {
    asm volatile("ldmatrix.sync.aligned.m8n8.x4.shared.b16 {%0,%1,%2,%3}, [%4];"
                 : "=r"(r[0]), "=r"(r[1]), "=r"(r[2]), "=r"(r[3]) : "r"(addr));
}

// Grid-wide barrier; SAFE because all CTAs are resident (persistent grid).
// Self-resets so CUDA-graph replays see identical initial state.
__device__ __forceinline__ void grid_barrier(int id, unsigned grid, int tid) {
    if (tid == 0) {
        __threadfence();                      // publish prior writes
        atomicAdd(&g_arr[id], 1u);
        while (atomicAdd(&g_arr[id], 0u) < grid) __nanosleep(64);
        __threadfence();                      // acquire
        unsigned d = atomicAdd(&g_dep[id], 1u) + 1u;
        if (d == grid) {                      // everyone passed the spin
            g_arr[id] = 0u;
            __threadfence();
            g_dep[id] = 0u;
        }
    }
    __syncthreads();
}

// ---------------------------------------------------------------------------
// Single fused persistent kernel: Phase A (zero hist + build X, tile-0 LDG
// overlapped) -> barrier -> Phase B (bk histogram) -> barrier -> Phase C
// (R14 HMMA GEMM: 128-thr CTAs, 3/SM, warp tile m16 x n32, X-hi hoisted).
__global__ __launch_bounds__(THREADS, 3)
void fused_kernel(const float* __restrict__ Z, const float* __restrict__ Q,
                  const float* __restrict__ W, const float* __restrict__ U,
                  const int* __restrict__ npi, const int* __restrict__ bk,
                  float* __restrict__ V,
                  int n_np, int n_bk, int n_atoms, int n_tiles) {
    extern __shared__ char smem[];
    const uint32_t sb = smem_u32(smem);
    const int tid = threadIdx.x;
    const int wid = tid >> 5, lane = tid & 31;
    const int bg = wid & 1;
    const int mg = wid >> 1;
    const int qr = lane >> 2, qc = lane & 3;
    const int r0 = mg * 16 + qr, r1 = r0 + 8;
    int* colsA = (int*)(smem + OFF_COLS);

    const int bid = blockIdx.x;
    const unsigned grid = gridDim.x;
    const int gstride = grid * THREADS;
    const int gid = bid * THREADS + tid;
    const int ntl = (n_tiles > bid) ? ((n_tiles - 1 - bid) / (int)grid + 1) : 0;

    // ---- strength-reduced load pipeline state (tile-invariant per thread) ----
    const int row0 = tid >> 5;
    const int kc   = (tid & 31) << 2;
    const float* psrc = ((kc < 64) ? (W + kc) : (U + (kc - 64))) +
                        (size_t)(bid * NTILE + row0) * 64;
    const size_t pstride = (size_t)grid * NTILE * 64;
    int nn = bid * NTILE + row0;
    const int nstep = (int)grid * NTILE;
    const uint32_t dA = sb + OFF_A + (row0 * PITCH + kc) * 2;

#define LDG_TILE(PF)                                                          \
    do {                                                                      \
        _Pragma("unroll")                                                     \
        for (int j = 0; j < 8; ++j)                                           \
            if (nn + 4 * j < n_np) (PF)[j] = *(const float4*)(psrc + j * 256);\
        psrc += pstride; nn += nstep;                                         \
    } while (0)

#define CVT_STS(PF, BUFSEL)                                                   \
    do {                                                                      \
        const uint32_t _d0 = dA + (BUFSEL) * ABUF;                            \
        _Pragma("unroll")                                                     \
        for (int j = 0; j < 8; ++j) {                                         \
            float4 v = (PF)[j];                                               \
            uint32_t h01 = packh(v.x, v.y), h23 = packh(v.z, v.w);            \
            __half2 H01 = *(__half2*)&h01, H23 = *(__half2*)&h23;             \
            uint32_t l01 = packh(v.x - __low2float(H01),                      \
                                 v.y - __high2float(H01));                    \
            uint32_t l23 = packh(v.z - __low2float(H23),                      \
                                 v.w - __high2float(H23));                    \
            uint32_t d = _d0 + j * (4 * PITCH * 2);                           \
            asm volatile("st.shared.v2.b32 [%0], {%1,%2};"                    \
                         :: "r"(d), "r"(h01), "r"(h23));                      \
            asm volatile("st.shared.v2.b32 [%0], {%1,%2};"                    \
                         :: "r"(d + AL_DELTA), "r"(l01), "r"(l23));           \
        }                                                                     \
    } while (0)

    // Issue tile-0 loads FIRST: DRAM latency overlaps the prep phases.
    float4 pf[8];
    if (ntl) LDG_TILE(pf);

    // ---- Phase A: zero hist + build X (fp16 hi/lo) ----
    {
        const int n4 = (n_atoms + 3) >> 2;
        float4 z4 = make_float4(0.f, 0.f, 0.f, 0.f);
        for (int g = gid; g < n4; g += gstride) ((float4*)g_hist)[g] = z4;
        for (int g = gid; g < B_DIM * K_DIM; g += gstride) {
            int b = g >> 7, k = g & 127;
            float s;
            if (k < 64) {
                s = 0.f;
#pragma unroll
                for (int e = 0; e < 16; ++e) s += Z[(b * 16 + e) * 64 + k];
            } else {
                s = Q[b * 64 + (k - 64)];
            }
            __half h = __float2half_rn(s);
            g_Xh[g] = h;
            g_Xl[g] = __float2half_rn(s - __half2float(h));
        }
    }
    grid_barrier(0, grid, tid);               // hist zeroed, X published

    // ---- Phase B: bk histogram ----
    for (int g = gid; g < n_bk; g += gstride)
        atomicAdd(&g_hist[bk[g]], 1.0f);
    grid_barrier(1, grid, tid);               // hist complete

    // ---- Phase C: GEMM (R14 core, unchanged) ----
    for (int idx = tid; idx < 4096; idx += THREADS) {
        int b = idx >> 6, kp = (idx & 63) * 2;
        uint32_t d = (b * PITCH + kp) * 2;
        *(uint32_t*)(smem + OFF_XH + d) = ((const uint32_t*)g_Xh)[idx];
        *(uint32_t*)(smem + OFF_XL + d) = ((const uint32_t*)g_Xl)[idx];
    }
    if (tid < NTILE && ntl) {
        int n = bid * NTILE + tid;
        colsA[tid] = (n < n_np) ? npi[n] : 0;
    }
    if (bid == 0 && tid < B_DIM)             // V[:,0]; CTA0 rewrites col 0 in-order
        V[(size_t)tid * n_atoms] = 1.0f + g_hist[0];
    __syncthreads();                          // X in smem visible

    const int arow = (lane & 7) + (((lane >> 3) & 1) << 3);
    const int acol = (lane >> 4) << 3;
    const uint32_t Aoff = ((mg * 16 + arow) * PITCH + acol) * 2;
    const int xr = (lane & 7) + ((lane >> 4) << 3);
    const int xc = ((lane >> 3) & 1) << 3;
    const uint32_t XH0 = sb + OFF_XH + ((bg * 32 + xr) * PITCH + xc) * 2;
    const uint32_t XL0 = sb + OFF_XL + ((bg * 32 + xr) * PITCH + xc) * 2;

    uint32_t bhr[64];
#pragma unroll
    for (int ks = 0; ks < 8; ++ks) {
        ldsm4(&bhr[ks * 8],     XH0 + ks * 32);
        ldsm4(&bhr[ks * 8 + 4], XH0 + NB_OFF + ks * 32);
    }

    if (ntl) CVT_STS(pf, 0);                  // buffer 0 <- tile 0

    const size_t na = (size_t)n_atoms;
    const size_t rbase = (size_t)(bg * 32 + 2 * qc) * na;
    const size_t step8 = 8 * na;

    for (int i = 0; i < ntl; ++i) {
        const int cur = i & 1, nxt = cur ^ 1;
        const int n0 = (bid + i * (int)grid) * NTILE;
        __syncthreads();                      // buf[cur] + cols[cur] visible

        if (i + 1 < ntl) {
            LDG_TILE(pf);
            if (tid < NTILE) {
                int n = (bid + (i + 1) * (int)grid) * NTILE + tid;
                colsA[nxt * 32 + tid] = (n < n_np) ? npi[n] : 0;
            }
        }
        const int* cols = colsA + cur * 32;
        const int  c0 = cols[r0], c1 = cols[r1];
        const float base0 = 0.5f + g_hist[c0];
        const float base1 = 0.5f + g_hist[c1];
        const bool o0 = (n0 + r0 < n_np), o1 = (n0 + r1 < n_np);

        const uint32_t AH = sb + OFF_A + cur * ABUF + Aoff;
        float d[4][4];
#pragma unroll
        for (int x = 0; x < 4; ++x)
#pragma unroll
            for (int j = 0; j < 4; ++j) d[x][j] = 0.f;

#pragma unroll
        for (int ks = 0; ks < 8; ++ks) {
            uint32_t ah[4], al[4], bl0[4], bl1[4];
            ldsm4(ah, AH + ks * 32);
            ldsm4(al, AH + AL_DELTA + ks * 32);
            ldsm4(bl0, XL0 + ks * 32);
            ldsm4(bl1, XL0 + NB_OFF + ks * 32);
            const uint32_t* bh0 = &bhr[ks * 8];
            const uint32_t* bh1 = bh0 + 4;
            mma16816(d[0], ah, bh0[0], bh0[1]);
            mma16816(d[1], ah, bh0[2], bh0[3]);
            mma16816(d[2], ah, bh1[0], bh1[1]);
            mma16816(d[3], ah, bh1[2], bh1[3]);
            mma16816(d[0], al, bh0[0], bh0[1]);
            mma16816(d[1], al, bh0[2], bh0[3]);
            mma16816(d[2], al, bh1[0], bh1[1]);
            mma16816(d[3], al, bh1[2], bh1[3]);
            mma16816(d[0], ah, bl0[0], bl0[1]);
            mma16816(d[1], ah, bl0[2], bl0[3]);
            mma16816(d[2], ah, bl1[0], bl1[1]);
            mma16816(d[3], ah, bl1[2], bl1[3]);
        }

        float* pc0 = V + c0;
        float* pc1 = V + c1;
        size_t ro = rbase;
#pragma unroll
        for (int nb = 0; nb < 4; ++nb) {
#pragma unroll
            for (int j = 0; j < 4; ++j) {
                float t;
                asm("tanh.approx.f32 %0, %1;" : "=f"(t) : "f"(0.5f * d[nb][j]));
                float v = fmaf(0.5f, t, (j >> 1) ? base1 : base0);
                float* p = ((j >> 1) ? pc1 : pc0) + ro + ((j & 1) ? na : 0);
                if ((j >> 1) ? o1 : o0) *p = v;
            }
            ro += step8;
        }

        if (i + 1 < ntl)
            CVT_STS(pf, nxt);
    }
#undef LDG_TILE
#undef CVT_STS

    // fused tail: V[b][c] = hist[c] for c in [n_np, n_atoms), grid-strided
    const int total4 = (n_atoms - n_np) >> 2;
    const float4* h4 = (const float4*)(g_hist + n_np);
    for (int t = gid; t < B_DIM * total4; t += gstride) {
        int b = t / total4, c4 = t - b * total4;
        ((float4*)(V + (size_t)b * n_atoms + n_np))[c4] = h4[c4];
    }
}

// ---------------------------------------------------------------------------
extern "C" void kernel_launch(void* const* d_in, const int* in_sizes, int n_in,
                              void* d_out, int out_size) {
    const float* Z   = (const float*)d_in[0];
    const float* Q   = (const float*)d_in[1];
    const float* W   = (const float*)d_in[2];
    const float* U   = (const float*)d_in[3];
    const int*   npi = (const int*)d_in[4];
    const int*   bk  = (const int*)d_in[5];
    const int n_np    = in_sizes[4];
    const int n_bk    = in_sizes[5];
    const int n_atoms = out_size / B_DIM;
    float* V = (float*)d_out;

    int nsm = 0;
    cudaDeviceGetAttribute(&nsm, cudaDevAttrMultiProcessorCount, 0);
    if (nsm <= 0) nsm = 148;
    cudaFuncSetAttribute(fused_kernel,
                         cudaFuncAttributeMaxDynamicSharedMemorySize, SMEM_TOTAL);

    int n_tiles = (n_np + NTILE - 1) / NTILE;
    int g = 3 * nsm < n_tiles ? 3 * nsm : n_tiles;   // ALL CTAs resident
    fused_kernel<<<g, THREADS, SMEM_TOTAL>>>(Z, Q, W, U, npi, bk, V,
                                             n_np, n_bk, n_atoms, n_tiles);
}

// round 16
// speedup vs baseline: 1.0907x; 1.0907x over previous
#include <cuda_runtime.h>
#include <cuda_fp16.h>
#include <cstdint>

// Shapes fixed by dataset: B=64, E=16, D=64, Q_DIM=64 -> K=128.
#define B_DIM    64
#define K_DIM    128
#define NTILE    32
#define THREADS  128
#define HIST_CAP 262144
#define PITCH    136           // halves per row (272B): ldsm conflict-free
#define ABUF     8704          // A-hi per buffer (32 rows x 136 halves)
#define NB_OFF   (16 * PITCH * 2)

// SMEM layout (bytes)
#define OFF_XH   0             // 64 x 136 halves = 17408
#define OFF_XL   17408
#define OFF_A    34816         // [Ah0][Ah1] = 2 x 8704
#define OFF_COLS 52224         // 2 x 32 ints
#define SMEM_TOTAL 52736

__device__ __half g_Xh[B_DIM * K_DIM];
__device__ __half g_Xl[B_DIM * K_DIM];
__device__ float  g_hist[HIST_CAP];

// ---------------------------------------------------------------------------
__device__ __forceinline__ uint32_t smem_u32(const void* p) {
    uint32_t a;
    asm("{ .reg .u64 t; cvta.to.shared.u64 t, %1; cvt.u32.u64 %0, t; }"
        : "=r"(a) : "l"(p));
    return a;
}

__device__ __forceinline__ uint32_t packh(float lo, float hi) {
    uint32_t r;
    asm("cvt.rn.f16x2.f32 %0, %1, %2;" : "=r"(r) : "f"(hi), "f"(lo));
    return r;
}

__device__ __forceinline__ void mma16816(float* d, const uint32_t* a,
                                         uint32_t b0, uint32_t b1) {
    asm volatile(
        "mma.sync.aligned.m16n8k16.row.col.f32.f16.f16.f32 "
        "{%0,%1,%2,%3}, {%4,%5,%6,%7}, {%8,%9}, {%0,%1,%2,%3};"
        : "+f"(d[0]), "+f"(d[1]), "+f"(d[2]), "+f"(d[3])
        : "r"(a[0]), "r"(a[1]), "r"(a[2]), "r"(a[3]), "r"(b0), "r"(b1));
}

__device__ __forceinline__ void ldsm4(uint32_t* r, uint32_t addr) {
    asm volatile("ldmatrix.sync.aligned.m8n8.x4.shared.b16 {%0,%1,%2,%3}, [%4];"
                 : "=r"(r[0]), "=r"(r[1]), "=r"(r[2]), "=r"(r[3]) : "r"(addr));
}

// ---------------------------------------------------------------------------
// Persistent HMMA GEMM: 128-thread CTAs, 3/SM. Warp tile m16 x n32, X-hi
// hoisted (64 regs). TWO-PASS fp16 split: s = Wh*Xh + Wh*Xl (Wl term dropped,
// ~2.8e-3 score noise -> ~1e-4 norm rel err). A stored hi-only in smem;
// LDG prefetch converts fp32->fp16 in registers (16 regs).
__global__ __launch_bounds__(THREADS, 3)
void gemm_kernel(const float* __restrict__ W, const float* __restrict__ U,
                 const int* __restrict__ npi, float* __restrict__ V,
                 int n_np, int n_atoms, int n_tiles) {
    extern __shared__ char smem[];
    const uint32_t sb = smem_u32(smem);
    const int tid = threadIdx.x;
    const int wid = tid >> 5, lane = tid & 31;
    const int bg = wid & 1;                  // b-group: 32 b-cols
    const int mg = wid >> 1;                 // m-group: 16 rows
    const int qr = lane >> 2, qc = lane & 3;
    const int r0 = mg * 16 + qr, r1 = r0 + 8;
    int* colsA = (int*)(smem + OFF_COLS);    // [2][32]

    // prologue: X (hi/lo fp16) -> smem
    for (int idx = tid; idx < 4096; idx += THREADS) {
        int b = idx >> 6, kp = (idx & 63) * 2;
        uint32_t d = (b * PITCH + kp) * 2;
        *(uint32_t*)(smem + OFF_XH + d) = ((const uint32_t*)g_Xh)[idx];
        *(uint32_t*)(smem + OFF_XL + d) = ((const uint32_t*)g_Xl)[idx];
    }

    const int bid = blockIdx.x, grid = gridDim.x;
    const int ntl = (n_tiles > bid) ? ((n_tiles - 1 - bid) / grid + 1) : 0;

    if (tid < NTILE && ntl) {
        int n = bid * NTILE + tid;
        colsA[tid] = (n < n_np) ? npi[n] : 0;
    }
    if (bid == 0 && tid < B_DIM)             // V[:,0]; CTA0 rewrites col 0 in-order
        V[(size_t)tid * n_atoms] = 1.0f + g_hist[0];
    __syncthreads();                          // X visible for hoist

    // lane addressing
    const int arow = (lane & 7) + (((lane >> 3) & 1) << 3);
    const int acol = (lane >> 4) << 3;
    const uint32_t Aoff = ((mg * 16 + arow) * PITCH + acol) * 2;
    const int xr = (lane & 7) + ((lane >> 4) << 3);
    const int xc = ((lane >> 3) & 1) << 3;
    const uint32_t XH0 = sb + OFF_XH + ((bg * 32 + xr) * PITCH + xc) * 2;
    const uint32_t XL0 = sb + OFF_XL + ((bg * 32 + xr) * PITCH + xc) * 2;

    // hoist ALL X-hi fragments: 8 ks x 2 nb16 x 4 regs = 64 registers
    uint32_t bhr[64];
#pragma unroll
    for (int ks = 0; ks < 8; ++ks) {
        ldsm4(&bhr[ks * 8],     XH0 + ks * 32);
        ldsm4(&bhr[ks * 8 + 4], XH0 + NB_OFF + ks * 32);
    }

    // --- strength-reduced load pipeline (tile-invariant per thread) ---
    const int row0 = tid >> 5;               // 0..3
    const int kc   = (tid & 31) << 2;        // 0..124
    const float* psrc = ((kc < 64) ? (W + kc) : (U + (kc - 64))) +
                        (size_t)(bid * NTILE + row0) * 64;
    const size_t pstride = (size_t)grid * NTILE * 64;
    int nn = bid * NTILE + row0;
    const int nstep = grid * NTILE;
    const uint32_t dA = sb + OFF_A + (row0 * PITCH + kc) * 2;

    // LDG + fp32->fp16 convert in registers (hi only): 16 regs
#define LDG_TILE(PH)                                                          \
    do {                                                                      \
        _Pragma("unroll")                                                     \
        for (int j = 0; j < 8; ++j)                                           \
            if (nn + 4 * j < n_np) {                                          \
                float4 v = *(const float4*)(psrc + j * 256);                  \
                (PH)[2 * j]     = packh(v.x, v.y);                            \
                (PH)[2 * j + 1] = packh(v.z, v.w);                            \
            }                                                                 \
        psrc += pstride; nn += nstep;                                         \
    } while (0)

#define STS_TILE(PH, BUFSEL)                                                  \
    do {                                                                      \
        const uint32_t _d0 = dA + (BUFSEL) * ABUF;                            \
        _Pragma("unroll")                                                     \
        for (int j = 0; j < 8; ++j)                                           \
            asm volatile("st.shared.v2.b32 [%0], {%1,%2};"                    \
                         :: "r"(_d0 + j * (4 * PITCH * 2)),                   \
                            "r"((PH)[2 * j]), "r"((PH)[2 * j + 1]));          \
    } while (0)

    uint32_t ph[16];
    if (ntl) {
        LDG_TILE(ph);
        STS_TILE(ph, 0);                     // buffer 0 <- tile 0
    }

    // --- epilogue address state (hoisted) ---
    const size_t na = (size_t)n_atoms;
    const size_t rbase = (size_t)(bg * 32 + 2 * qc) * na;
    const size_t step8 = 8 * na;

    for (int i = 0; i < ntl; ++i) {
        const int cur = i & 1, nxt = cur ^ 1;
        const int n0 = (bid + i * grid) * NTILE;
        __syncthreads();                     // buf[cur] + cols[cur] visible

        if (i + 1 < ntl) {
            LDG_TILE(ph);
            if (tid < NTILE) {
                int n = (bid + (i + 1) * grid) * NTILE + tid;
                colsA[nxt * 32 + tid] = (n < n_np) ? npi[n] : 0;
            }
        }
        const int* cols = colsA + cur * 32;
        const int  c0 = cols[r0], c1 = cols[r1];
        const float base0 = 0.5f + g_hist[c0];
        const float base1 = 0.5f + g_hist[c1];
        const bool o0 = (n0 + r0 < n_np), o1 = (n0 + r1 < n_np);

        const uint32_t AH = sb + OFF_A + cur * ABUF + Aoff;
        float d[4][4];                        // 4 n8-blocks across n32
#pragma unroll
        for (int x = 0; x < 4; ++x)
#pragma unroll
            for (int j = 0; j < 4; ++j) d[x][j] = 0.f;

#pragma unroll
        for (int ks = 0; ks < 8; ++ks) {
            uint32_t ah[4], bl0[4], bl1[4];
            ldsm4(ah, AH + ks * 32);
            ldsm4(bl0, XL0 + ks * 32);
            ldsm4(bl1, XL0 + NB_OFF + ks * 32);
            const uint32_t* bh0 = &bhr[ks * 8];
            const uint32_t* bh1 = bh0 + 4;
            // 8 MMAs, 4 chains: hh pass + hl pass
            mma16816(d[0], ah, bh0[0], bh0[1]);
            mma16816(d[1], ah, bh0[2], bh0[3]);
            mma16816(d[2], ah, bh1[0], bh1[1]);
            mma16816(d[3], ah, bh1[2], bh1[3]);
            mma16816(d[0], ah, bl0[0], bl0[1]);
            mma16816(d[1], ah, bl0[2], bl0[3]);
            mma16816(d[2], ah, bl1[0], bl1[1]);
            mma16816(d[3], ah, bl1[2], bl1[3]);
        }

        // epilogue: sigmoid = 0.5 + 0.5*tanh(s/2) + hist, direct scatter.
        // Fixed (nb,j): 4 b-rows x 8 consecutive n -> 4 full 32B sectors.
        float* pc0 = V + c0;
        float* pc1 = V + c1;
        size_t ro = rbase;
#pragma unroll
        for (int nb = 0; nb < 4; ++nb) {
#pragma unroll
            for (int j = 0; j < 4; ++j) {
                float t;
                asm("tanh.approx.f32 %0, %1;" : "=f"(t) : "f"(0.5f * d[nb][j]));
                float v = fmaf(0.5f, t, (j >> 1) ? base1 : base0);
                float* p = ((j >> 1) ? pc1 : pc0) + ro + ((j & 1) ? na : 0);
                if ((j >> 1) ? o1 : o0) *p = v;
            }
            ro += step8;
        }

        if (i + 1 < ntl)
            STS_TILE(ph, nxt);
        // next top-of-loop barrier orders STS_TILE before its ldsm readers
    }
#undef LDG_TILE
#undef STS_TILE

    // fused tail: V[b][c] = hist[c] for c in [n_np, n_atoms), grid-strided
    const int total4 = (n_atoms - n_np) >> 2;
    const float4* h4 = (const float4*)(g_hist + n_np);
    for (int t = bid * THREADS + tid; t < B_DIM * total4; t += grid * THREADS) {
        int b = t / total4, c4 = t - b * total4;
        ((float4*)(V + (size_t)b * n_atoms + n_np))[c4] = h4[c4];
    }
}

// ---------------------------------------------------------------------------
// fused: blocks 0-63 build X (fp16 hi/lo); remaining blocks do bk histogram.
// (g_hist zeroed beforehand via cudaMemsetAsync.)
__global__ void prep_hist_kernel(const float* __restrict__ Z,
                                 const float* __restrict__ Q,
                                 const int* __restrict__ bk, int n_bk) {
    if (blockIdx.x < B_DIM) {
        int b = blockIdx.x, k = threadIdx.x;
        if (k < K_DIM) {
            float s;
            if (k < 64) {
                s = 0.f;
#pragma unroll
                for (int e = 0; e < 16; ++e) s += Z[(b * 16 + e) * 64 + k];
            } else {
                s = Q[b * 64 + (k - 64)];
            }
            __half h = __float2half_rn(s);
            g_Xh[b * K_DIM + k] = h;
            g_Xl[b * K_DIM + k] = __float2half_rn(s - __half2float(h));
        }
    } else {
        int i = (blockIdx.x - B_DIM) * blockDim.x + threadIdx.x;
        if (i < n_bk) atomicAdd(&g_hist[bk[i]], 1.0f);
    }
}

// ---------------------------------------------------------------------------
extern "C" void kernel_launch(void* const* d_in, const int* in_sizes, int n_in,
                              void* d_out, int out_size) {
    const float* Z   = (const float*)d_in[0];
    const float* Q   = (const float*)d_in[1];
    const float* W   = (const float*)d_in[2];
    const float* U   = (const float*)d_in[3];
    const int*   npi = (const int*)d_in[4];
    const int*   bk  = (const int*)d_in[5];
    const int n_np    = in_sizes[4];
    const int n_bk    = in_sizes[5];
    const int n_atoms = out_size / B_DIM;
    float* V = (float*)d_out;

    int nsm = 0;
    cudaDeviceGetAttribute(&nsm, cudaDevAttrMultiProcessorCount, 0);
    if (nsm <= 0) nsm = 148;
    cudaFuncSetAttribute(gemm_kernel,
                         cudaFuncAttributeMaxDynamicSharedMemorySize, SMEM_TOTAL);

    void* hist_ptr = nullptr;
    cudaGetSymbolAddress(&hist_ptr, g_hist);
    cudaMemsetAsync(hist_ptr, 0, (size_t)n_atoms * sizeof(float), 0);

    int hb = (n_bk + 127) / 128;
    prep_hist_kernel<<<B_DIM + hb, 128>>>(Z, Q, bk, n_bk);

    int n_tiles = (n_np + NTILE - 1) / NTILE;
    int g = 3 * nsm < n_tiles ? 3 * nsm : n_tiles;
    gemm_kernel<<<g, THREADS, SMEM_TOTAL>>>(W, U, npi, V, n_np, n_atoms, n_tiles);
}